// round 12
// baseline (speedup 1.0000x reference)
#include <cuda_runtime.h>
#include <cstdint>

#define N_ROWS 1024
#define M_ROWS 1024
#define DIM    512
#define BTN    32           // CTA tile edge (n and m)
#define KC     32
#define NCH    (DIM / KC)   // 16 chunks
#define PADK   36           // row stride 144B; stride-8 rows -> conflict-free LDS.128

using u64 = unsigned long long;

__device__ float g_zn[N_ROWS];     // ||z_n||^2
__device__ float g_zprn[M_ROWS];   // ||zpr_m||^2
__device__ float g_zs[N_ROWS];     // sum z_n
__device__ float g_zprs[M_ROWS];   // sum zpr_m

// packed fp32 ops: 1 issue slot, 2 fma-pipe slots (double-pumped)
#define FMA2ACC(acc, a, b) asm("fma.rn.f32x2 %0, %1, %2, %0;" : "+l"(acc) : "l"(a), "l"(b))
#define ADD2ACC(acc, x)    asm("add.rn.f32x2 %0, %0, %1;"     : "+l"(acc) : "l"(x))

__device__ __forceinline__ void upk(float& x, float& y, u64 v) {
    asm("mov.b64 {%0, %1}, %2;" : "=f"(x), "=f"(y) : "l"(v));
}

__device__ __forceinline__ void cp16(uint32_t smem, const void* g) {
    asm volatile("cp.async.cg.shared.global [%0], [%1], 16;" :: "r"(smem), "l"(g));
}
#define CP_COMMIT() asm volatile("cp.async.commit_group;")
#define CP_WAIT0()  asm volatile("cp.async.wait_group 0;")

union U2 { ulonglong2 v; u64 p[2]; float f[4]; };
union PF { u64 p; float f[2]; };

// One warp per row: sum + squared-norm.
__global__ void norms_kernel(const float* __restrict__ z, const float* __restrict__ zpr) {
    int warp = (blockIdx.x * blockDim.x + threadIdx.x) >> 5;
    int lane = threadIdx.x & 31;
    if (warp >= N_ROWS + M_ROWS) return;
    const float* src = (warp < N_ROWS) ? (z + (size_t)warp * DIM)
                                       : (zpr + (size_t)(warp - N_ROWS) * DIM);
    float s = 0.0f, q = 0.0f;
    #pragma unroll
    for (int i = 0; i < DIM / 32; ++i) {
        float v = src[i * 32 + lane];
        s += v;
        q = fmaf(v, v, q);
    }
    #pragma unroll
    for (int o = 16; o; o >>= 1) {
        s += __shfl_xor_sync(0xffffffffu, s, o);
        q += __shfl_xor_sync(0xffffffffu, q, o);
    }
    if (lane == 0) {
        if (warp < N_ROWS) { g_zn[warp] = q; g_zs[warp] = s; }
        else               { g_zprn[warp - N_ROWS] = q; g_zprs[warp - N_ROWS] = s; }
    }
}

// 64 threads, 4x4 cells each. dp via packed FFMA2; lm via FMNMX pairs + packed ADD2.
// l1 = 2*lm - Sa - Sb; l2 = sqrt(|a|^2+|b|^2-2dp). out[m][n][3] = {l1, l2, dp}
__global__ __launch_bounds__(64, 8)
void pair_kernel(const float* __restrict__ z,
                 const float* __restrict__ zpr,
                 float* __restrict__ out) {
    __shared__ __align__(16) float as[2][BTN][PADK];
    __shared__ __align__(16) float bs[2][BTN][PADK];

    const int tid = threadIdx.x;
    const int tx = tid & 7;     // n rows: tx + 8*i, i<4
    const int ty = tid >> 3;    // m rows: ty + 8*j, j<4
    const int n0 = blockIdx.x * BTN;
    const int m0 = blockIdx.y * BTN;

    // staging: 64 threads x 4 cp16 per array = 32 rows x 32 k each
    const int scol = (tid & 7) * 4;
    const int srow = tid >> 3;            // 0..7, rows srow + 8r
    const float* gz  = z   + (size_t)(n0 + srow) * DIM + scol;
    const float* gzp = zpr + (size_t)(m0 + srow) * DIM + scol;

    uint32_t sa = (uint32_t)__cvta_generic_to_shared(&as[0][srow][scol]);
    uint32_t sb = (uint32_t)__cvta_generic_to_shared(&bs[0][srow][scol]);
    const uint32_t ROWOFF = (uint32_t)(8 * PADK * sizeof(float));
    const uint32_t BUFOFF = (uint32_t)(BTN * PADK * sizeof(float));

    u64 dpn[4][4];   // packed dot accumulators
    u64 lm2[4][4];   // packed sum of max(a,b)
    #pragma unroll
    for (int i = 0; i < 4; ++i)
        #pragma unroll
        for (int j = 0; j < 4; ++j) { dpn[i][j] = 0ull; lm2[i][j] = 0ull; }

    // prefetch chunk 0 into buffer 0
    #pragma unroll
    for (int r = 0; r < 4; ++r) {
        cp16(sa + r * ROWOFF, gz  + (size_t)(8 * r) * DIM);
        cp16(sb + r * ROWOFF, gzp + (size_t)(8 * r) * DIM);
    }
    CP_COMMIT();

    for (int c = 0; c < NCH; ++c) {
        CP_WAIT0();
        __syncthreads();

        if (c + 1 < NCH) {
            uint32_t o = ((c + 1) & 1) * BUFOFF;
            const float* pz  = gz  + (c + 1) * KC;
            const float* pzp = gzp + (c + 1) * KC;
            #pragma unroll
            for (int r = 0; r < 4; ++r) {
                cp16(sa + o + r * ROWOFF, pz  + (size_t)(8 * r) * DIM);
                cp16(sb + o + r * ROWOFF, pzp + (size_t)(8 * r) * DIM);
            }
            CP_COMMIT();
        }

        const int s = c & 1;
        #pragma unroll
        for (int kk = 0; kk < KC; kk += 4) {
            U2 A[4], B[4];
            #pragma unroll
            for (int i = 0; i < 4; ++i)
                A[i].v = *(const ulonglong2*)&as[s][tx + 8 * i][kk];   // LDS.128
            #pragma unroll
            for (int j = 0; j < 4; ++j)
                B[j].v = *(const ulonglong2*)&bs[s][ty + 8 * j][kk];   // broadcast

            #pragma unroll
            for (int i = 0; i < 4; ++i) {
                #pragma unroll
                for (int j = 0; j < 4; ++j) {
                    FMA2ACC(dpn[i][j], A[i].p[0], B[j].p[0]);   // dp: 2 elems/issue
                    FMA2ACC(dpn[i][j], A[i].p[1], B[j].p[1]);
                    PF m0, m1;                                  // FMNMX into pair halves
                    m0.f[0] = fmaxf(A[i].f[0], B[j].f[0]);
                    m0.f[1] = fmaxf(A[i].f[1], B[j].f[1]);
                    m1.f[0] = fmaxf(A[i].f[2], B[j].f[2]);
                    m1.f[1] = fmaxf(A[i].f[3], B[j].f[3]);
                    ADD2ACC(lm2[i][j], m0.p);                   // lm += max: 2 elems/issue
                    ADD2ACC(lm2[i][j], m1.p);
                }
            }
        }
        __syncthreads();
    }

    // epilogue
    float zn[4], zs[4], pn[4], ps[4];
    #pragma unroll
    for (int i = 0; i < 4; ++i) { zn[i] = g_zn[n0 + tx + 8 * i]; zs[i] = g_zs[n0 + tx + 8 * i]; }
    #pragma unroll
    for (int j = 0; j < 4; ++j) { pn[j] = g_zprn[m0 + ty + 8 * j]; ps[j] = g_zprs[m0 + ty + 8 * j]; }

    #pragma unroll
    for (int j = 0; j < 4; ++j) {
        #pragma unroll
        for (int i = 0; i < 4; ++i) {
            float dlo, dhi, mlo, mhi;
            upk(dlo, dhi, dpn[i][j]);
            upk(mlo, mhi, lm2[i][j]);
            float dp = dlo + dhi;
            float lm = mlo + mhi;
            float l1 = 2.0f * lm - zs[i] - ps[j];
            float l2 = sqrtf(fmaxf(zn[i] + pn[j] - 2.0f * dp, 0.0f));
            int n = n0 + tx + 8 * i;
            int m = m0 + ty + 8 * j;
            float* o = out + ((size_t)m * N_ROWS + n) * 3;
            o[0] = l1;
            o[1] = l2;
            o[2] = dp;
        }
    }
}

extern "C" void kernel_launch(void* const* d_in, const int* in_sizes, int n_in,
                              void* d_out, int out_size) {
    const float* z   = (const float*)d_in[0];
    const float* zpr = (const float*)d_in[1];
    float* out = (float*)d_out;

    norms_kernel<<<(N_ROWS + M_ROWS) * 32 / 256, 256>>>(z, zpr);

    dim3 grid(N_ROWS / BTN, M_ROWS / BTN);
    pair_kernel<<<grid, 64>>>(z, zpr, out);
}

// round 13
// speedup vs baseline: 1.1246x; 1.1246x over previous
#include <cuda_runtime.h>
#include <cstdint>

#define N_ROWS 1024
#define M_ROWS 1024
#define DIM    512
#define BTN    32           // tile edge (n and m)
#define KC     32
#define NCH    (DIM / KC)   // 16 chunks
#define PADK   36           // row stride 144B; conflict-free LDS.128

using u64 = unsigned long long;

__device__ float g_zn[N_ROWS];     // ||z_n||^2
__device__ float g_zprn[M_ROWS];   // ||zpr_m||^2
__device__ float g_zs[N_ROWS];     // sum z_n
__device__ float g_zprs[M_ROWS];   // sum zpr_m

// packed fp32 ops: 1 issue slot, 2 fma-pipe slots (double-pumped)
#define FMA2ACC(acc, a, b) asm("fma.rn.f32x2 %0, %1, %2, %0;" : "+l"(acc) : "l"(a), "l"(b))
#define ADD2ACC(acc, x)    asm("add.rn.f32x2 %0, %0, %1;"     : "+l"(acc) : "l"(x))

__device__ __forceinline__ void upk(float& x, float& y, u64 v) {
    asm("mov.b64 {%0, %1}, %2;" : "=f"(x), "=f"(y) : "l"(v));
}

__device__ __forceinline__ void cp16(uint32_t smem, const void* g) {
    asm volatile("cp.async.cg.shared.global [%0], [%1], 16;" :: "r"(smem), "l"(g));
}
#define CP_COMMIT() asm volatile("cp.async.commit_group;")
#define CP_WAIT0()  asm volatile("cp.async.wait_group 0;")

union U2 { ulonglong2 v; u64 p[2]; float f[4]; };   // register-aliased views
union PF { u64 p; float f[2]; };

// One warp per row: sum + squared-norm.
__global__ void norms_kernel(const float* __restrict__ z, const float* __restrict__ zpr) {
    int warp = (blockIdx.x * blockDim.x + threadIdx.x) >> 5;
    int lane = threadIdx.x & 31;
    if (warp >= N_ROWS + M_ROWS) return;
    const float* src = (warp < N_ROWS) ? (z + (size_t)warp * DIM)
                                       : (zpr + (size_t)(warp - N_ROWS) * DIM);
    float s = 0.0f, q = 0.0f;
    #pragma unroll
    for (int i = 0; i < DIM / 32; ++i) {
        float v = src[i * 32 + lane];
        s += v;
        q = fmaf(v, v, q);
    }
    #pragma unroll
    for (int o = 16; o; o >>= 1) {
        s += __shfl_xor_sync(0xffffffffu, s, o);
        q += __shfl_xor_sync(0xffffffffu, q, o);
    }
    if (lane == 0) {
        if (warp < N_ROWS) { g_zn[warp] = q; g_zs[warp] = s; }
        else               { g_zprn[warp - N_ROWS] = q; g_zprs[warp - N_ROWS] = s; }
    }
}

// 128 threads, 4x2 cells. dp via packed FFMA2; lm via FMNMX pairs + packed ADD2.
// l1 = 2*lm - Sa - Sb; l2 = sqrt(|a|^2+|b|^2-2dp). out[m][n][3] = {l1, l2, dp}
__global__ __launch_bounds__(128, 6)
void pair_kernel(const float* __restrict__ z,
                 const float* __restrict__ zpr,
                 float* __restrict__ out) {
    __shared__ __align__(16) float as[2][BTN][PADK];
    __shared__ __align__(16) float bs[2][BTN][PADK];

    const int tid = threadIdx.x;
    const int tx = tid & 7;     // n rows: tx + 8*i, i<4
    const int ty = tid >> 3;    // m rows: ty + 16*j, j<2
    const int n0 = blockIdx.x * BTN;
    const int m0 = blockIdx.y * BTN;

    const int scol = (tid & 7) * 4;
    const int srow = tid >> 3;            // 0..15, plus +16
    const float* gz  = z   + (size_t)(n0 + srow) * DIM + scol;
    const float* gzp = zpr + (size_t)(m0 + srow) * DIM + scol;

    uint32_t sa0 = (uint32_t)__cvta_generic_to_shared(&as[0][srow][scol]);
    uint32_t sa1 = (uint32_t)__cvta_generic_to_shared(&as[0][srow + 16][scol]);
    uint32_t sb0 = (uint32_t)__cvta_generic_to_shared(&bs[0][srow][scol]);
    uint32_t sb1 = (uint32_t)__cvta_generic_to_shared(&bs[0][srow + 16][scol]);
    const uint32_t BUFOFF = (uint32_t)(BTN * PADK * sizeof(float));

    u64 dpn[4][2];   // packed dot accumulators
    u64 lm2[4][2];   // packed sum of max(a,b)
    #pragma unroll
    for (int i = 0; i < 4; ++i)
        #pragma unroll
        for (int j = 0; j < 2; ++j) { dpn[i][j] = 0ull; lm2[i][j] = 0ull; }

    // prefetch chunk 0 into buffer 0
    cp16(sa0, gz);            cp16(sa1, gz  + (size_t)16 * DIM);
    cp16(sb0, gzp);           cp16(sb1, gzp + (size_t)16 * DIM);
    CP_COMMIT();

    for (int c = 0; c < NCH; ++c) {
        CP_WAIT0();
        __syncthreads();

        if (c + 1 < NCH) {
            uint32_t o = ((c + 1) & 1) * BUFOFF;
            const float* pz  = gz  + (c + 1) * KC;
            const float* pzp = gzp + (c + 1) * KC;
            cp16(sa0 + o, pz);   cp16(sa1 + o, pz  + (size_t)16 * DIM);
            cp16(sb0 + o, pzp);  cp16(sb1 + o, pzp + (size_t)16 * DIM);
            CP_COMMIT();
        }

        const int s = c & 1;
        #pragma unroll
        for (int kk = 0; kk < KC; kk += 4) {
            U2 A[4], B[2];
            #pragma unroll
            for (int i = 0; i < 4; ++i)
                A[i].v = *(const ulonglong2*)&as[s][tx + 8 * i][kk];    // LDS.128
            #pragma unroll
            for (int j = 0; j < 2; ++j)
                B[j].v = *(const ulonglong2*)&bs[s][ty + 16 * j][kk];   // broadcast

            #pragma unroll
            for (int i = 0; i < 4; ++i) {
                #pragma unroll
                for (int j = 0; j < 2; ++j) {
                    FMA2ACC(dpn[i][j], A[i].p[0], B[j].p[0]);   // dp: 2 elems/issue (fma)
                    FMA2ACC(dpn[i][j], A[i].p[1], B[j].p[1]);
                    PF m0, m1;                                  // FMNMX (alu) into pairs
                    m0.f[0] = fmaxf(A[i].f[0], B[j].f[0]);
                    m0.f[1] = fmaxf(A[i].f[1], B[j].f[1]);
                    m1.f[0] = fmaxf(A[i].f[2], B[j].f[2]);
                    m1.f[1] = fmaxf(A[i].f[3], B[j].f[3]);
                    ADD2ACC(lm2[i][j], m0.p);                   // lm += max: 2 elems/issue
                    ADD2ACC(lm2[i][j], m1.p);
                }
            }
        }
        __syncthreads();
    }

    // epilogue
    float zn[4], zs[4], pn[2], ps[2];
    #pragma unroll
    for (int i = 0; i < 4; ++i) { zn[i] = g_zn[n0 + tx + 8 * i]; zs[i] = g_zs[n0 + tx + 8 * i]; }
    #pragma unroll
    for (int j = 0; j < 2; ++j) { pn[j] = g_zprn[m0 + ty + 16 * j]; ps[j] = g_zprs[m0 + ty + 16 * j]; }

    #pragma unroll
    for (int j = 0; j < 2; ++j) {
        #pragma unroll
        for (int i = 0; i < 4; ++i) {
            float dlo, dhi, mlo, mhi;
            upk(dlo, dhi, dpn[i][j]);
            upk(mlo, mhi, lm2[i][j]);
            float dp = dlo + dhi;
            float lm = mlo + mhi;
            float l1 = 2.0f * lm - zs[i] - ps[j];
            float l2 = sqrtf(fmaxf(zn[i] + pn[j] - 2.0f * dp, 0.0f));
            int n = n0 + tx + 8 * i;
            int m = m0 + ty + 16 * j;
            float* o = out + ((size_t)m * N_ROWS + n) * 3;
            o[0] = l1;
            o[1] = l2;
            o[2] = dp;
        }
    }
}

extern "C" void kernel_launch(void* const* d_in, const int* in_sizes, int n_in,
                              void* d_out, int out_size) {
    const float* z   = (const float*)d_in[0];
    const float* zpr = (const float*)d_in[1];
    float* out = (float*)d_out;

    norms_kernel<<<(N_ROWS + M_ROWS) * 32 / 256, 256>>>(z, zpr);

    dim3 grid(N_ROWS / BTN, M_ROWS / BTN);
    pair_kernel<<<grid, 128>>>(z, zpr, out);
}